// round 3
// baseline (speedup 1.0000x reference)
#include <cuda_runtime.h>

// ---------------------------------------------------------------------------
// MWDLSTMGCT: only the low-pass wavelet chain + LSTM-3 affect the output.
//   xl1 = avgpool2(sigmoid(x @ W1L^T + b1L))        (256 x 512)
//   xl2 = avgpool2(sigmoid(xl1 @ W2L^T + b2L))      (256 x 256)
//   h   = LSTM(xl2 as scalar sequence; Wih3,Whh3,b3), final hidden (256 x 100)
//   out = h @ Wout^T + bout                          (256 x 1)
// ---------------------------------------------------------------------------

#define NBATCH 256
#define HID    100
#define GATES  400   // 4*HID
#define TSTEPS 256

__device__ __align__(16) float g_xl1[256 * 512];
__device__ __align__(16) float g_xl2[256 * 256];

// ---------------------------------------------------------------------------
// Fused GEMM (C = A @ W^T), bias, sigmoid, avgpool2 along N.
// Tile 64(M) x 64(N), K-slices of 16, double-buffered smem, 4x4 microtile.
// A: [256][K], W: [N][K], out: [256][N/2]
// ---------------------------------------------------------------------------
template <int K>
__device__ __forceinline__ void gemm_sig_pool_body(
    const float* __restrict__ A, const float* __restrict__ W,
    const float* __restrict__ bias, float* __restrict__ out, int halfN)
{
    __shared__ __align__(16) float As[2][16][64];
    __shared__ __align__(16) float Bs[2][16][64];

    const int m0 = blockIdx.y * 64;
    const int n0 = blockIdx.x * 64;
    const int tid = threadIdx.x;
    const int lm = tid >> 2;            // 0..63  (row within tile for loads)
    const int lk = (tid & 3) * 4;       // 0,4,8,12 (k within slice)
    const int tx = tid & 15;            // 0..15
    const int ty = tid >> 4;            // 0..15

    const float* Aptr = A + (m0 + lm) * K + lk;
    const float* Wptr = W + (n0 + lm) * K + lk;

    float4 a4 = *(const float4*)(Aptr);
    float4 b4 = *(const float4*)(Wptr);
    As[0][lk + 0][lm] = a4.x; As[0][lk + 1][lm] = a4.y;
    As[0][lk + 2][lm] = a4.z; As[0][lk + 3][lm] = a4.w;
    Bs[0][lk + 0][lm] = b4.x; Bs[0][lk + 1][lm] = b4.y;
    Bs[0][lk + 2][lm] = b4.z; Bs[0][lk + 3][lm] = b4.w;
    __syncthreads();

    float acc[4][4] = {};
    const int NT = K / 16;

    for (int tI = 0; tI < NT; tI++) {
        const int cur = tI & 1;
        if (tI + 1 < NT) {
            a4 = *(const float4*)(Aptr + (tI + 1) * 16);
            b4 = *(const float4*)(Wptr + (tI + 1) * 16);
        }
        #pragma unroll
        for (int kk = 0; kk < 16; kk++) {
            float4 av = *(const float4*)&As[cur][kk][ty * 4];
            float4 bv = *(const float4*)&Bs[cur][kk][tx * 4];
            acc[0][0] = fmaf(av.x, bv.x, acc[0][0]);
            acc[0][1] = fmaf(av.x, bv.y, acc[0][1]);
            acc[0][2] = fmaf(av.x, bv.z, acc[0][2]);
            acc[0][3] = fmaf(av.x, bv.w, acc[0][3]);
            acc[1][0] = fmaf(av.y, bv.x, acc[1][0]);
            acc[1][1] = fmaf(av.y, bv.y, acc[1][1]);
            acc[1][2] = fmaf(av.y, bv.z, acc[1][2]);
            acc[1][3] = fmaf(av.y, bv.w, acc[1][3]);
            acc[2][0] = fmaf(av.z, bv.x, acc[2][0]);
            acc[2][1] = fmaf(av.z, bv.y, acc[2][1]);
            acc[2][2] = fmaf(av.z, bv.z, acc[2][2]);
            acc[2][3] = fmaf(av.z, bv.w, acc[2][3]);
            acc[3][0] = fmaf(av.w, bv.x, acc[3][0]);
            acc[3][1] = fmaf(av.w, bv.y, acc[3][1]);
            acc[3][2] = fmaf(av.w, bv.z, acc[3][2]);
            acc[3][3] = fmaf(av.w, bv.w, acc[3][3]);
        }
        if (tI + 1 < NT) {
            const int nb = cur ^ 1;
            As[nb][lk + 0][lm] = a4.x; As[nb][lk + 1][lm] = a4.y;
            As[nb][lk + 2][lm] = a4.z; As[nb][lk + 3][lm] = a4.w;
            Bs[nb][lk + 0][lm] = b4.x; Bs[nb][lk + 1][lm] = b4.y;
            Bs[nb][lk + 2][lm] = b4.z; Bs[nb][lk + 3][lm] = b4.w;
        }
        __syncthreads();
    }

    const float bn0 = bias[n0 + tx * 4 + 0];
    const float bn1 = bias[n0 + tx * 4 + 1];
    const float bn2 = bias[n0 + tx * 4 + 2];
    const float bn3 = bias[n0 + tx * 4 + 3];
    const int ocol = (n0 + tx * 4) >> 1;
    #pragma unroll
    for (int i = 0; i < 4; i++) {
        const int m = m0 + ty * 4 + i;
        float s0 = 1.f / (1.f + __expf(-(acc[i][0] + bn0)));
        float s1 = 1.f / (1.f + __expf(-(acc[i][1] + bn1)));
        float s2 = 1.f / (1.f + __expf(-(acc[i][2] + bn2)));
        float s3 = 1.f / (1.f + __expf(-(acc[i][3] + bn3)));
        out[m * halfN + ocol + 0] = 0.5f * (s0 + s1);
        out[m * halfN + ocol + 1] = 0.5f * (s2 + s3);
    }
}

__global__ void __launch_bounds__(256) gemm1_kernel(
    const float* __restrict__ A, const float* __restrict__ W,
    const float* __restrict__ bias)
{
    gemm_sig_pool_body<1024>(A, W, bias, g_xl1, 512);
}

__global__ void __launch_bounds__(256) gemm2_kernel(
    const float* __restrict__ W, const float* __restrict__ bias)
{
    gemm_sig_pool_body<512>(g_xl1, W, bias, g_xl2, 256);
}

// ---------------------------------------------------------------------------
// LSTM-3, persistent per-CTA, 2 batch rows per CTA, weights in registers.
// 416 threads; threads 0..399 each own gate g (Whh[g][0..99] in regs),
// threads 0..99 additionally own the cell state for lane j of both rows.
// ---------------------------------------------------------------------------
__device__ __forceinline__ float sigf(float x) { return 1.f / (1.f + __expf(-x)); }

__global__ void __launch_bounds__(416, 1) lstm_kernel(
    const float* __restrict__ Wih, const float* __restrict__ Whh,
    const float* __restrict__ b3,  const float* __restrict__ Wout,
    const float* __restrict__ bout, float* __restrict__ out)
{
    const int r0 = blockIdx.x * 2;
    const int t = threadIdx.x;

    __shared__ __align__(8) float2 h_s[HID];
    __shared__ float z_s[2][GATES];
    __shared__ float x_s[2][TSTEPS];
    __shared__ float red0[HID], red1[HID];

    float wreg[HID];
    float wih_g = 0.f, bg = 0.f;
    if (t < GATES) {
        #pragma unroll
        for (int k = 0; k < HID; k++) wreg[k] = Whh[t * HID + k];
        wih_g = Wih[t];
        bg = b3[t];
    }
    if (t < TSTEPS) {
        x_s[0][t] = g_xl2[r0 * TSTEPS + t];
        x_s[1][t] = g_xl2[(r0 + 1) * TSTEPS + t];
    }
    if (t < HID) h_s[t] = make_float2(0.f, 0.f);
    float c0 = 0.f, c1 = 0.f;
    __syncthreads();

    for (int step = 0; step < TSTEPS; step++) {
        if (t < GATES) {
            float z0 = fmaf(wih_g, x_s[0][step], bg);
            float z1 = fmaf(wih_g, x_s[1][step], bg);
            #pragma unroll
            for (int k = 0; k < HID; k++) {
                float2 h = h_s[k];
                z0 = fmaf(wreg[k], h.x, z0);
                z1 = fmaf(wreg[k], h.y, z1);
            }
            z_s[0][t] = z0;
            z_s[1][t] = z1;
        }
        __syncthreads();
        if (t < HID) {
            float i0 = z_s[0][t], f0 = z_s[0][HID + t];
            float g0 = z_s[0][2 * HID + t], o0 = z_s[0][3 * HID + t];
            c0 = sigf(f0) * c0 + sigf(i0) * tanhf(g0);
            float h0 = sigf(o0) * tanhf(c0);
            float i1 = z_s[1][t], f1 = z_s[1][HID + t];
            float g1 = z_s[1][2 * HID + t], o1 = z_s[1][3 * HID + t];
            c1 = sigf(f1) * c1 + sigf(i1) * tanhf(g1);
            float h1 = sigf(o1) * tanhf(c1);
            h_s[t] = make_float2(h0, h1);
        }
        __syncthreads();
    }

    // Final projection: out[r] = h_final . Wout + bout
    if (t < HID) {
        float w = Wout[t];
        red0[t] = h_s[t].x * w;
        red1[t] = h_s[t].y * w;
    }
    __syncthreads();
    if (t == 0) {
        float s = bout[0];
        for (int k = 0; k < HID; k++) s += red0[k];
        out[r0] = s;
    }
    if (t == 1) {
        float s = bout[0];
        for (int k = 0; k < HID; k++) s += red1[k];
        out[r0 + 1] = s;
    }
}

// ---------------------------------------------------------------------------
// Launch. Input order (metadata.txt): x, W1H, b1H, W1L, b1L, W2H, b2H, W2L,
// b2L, Wih1, Whh1, b1, Wih2, Whh2, b2, Wih3, Whh3, b3, Wout, bout.
// Only the low-pass + LSTM-3 inputs are used.
// ---------------------------------------------------------------------------
extern "C" void kernel_launch(void* const* d_in, const int* in_sizes, int n_in,
                              void* d_out, int out_size)
{
    const float* x    = (const float*)d_in[0];
    const float* W1L  = (const float*)d_in[3];
    const float* b1L  = (const float*)d_in[4];
    const float* W2L  = (const float*)d_in[7];
    const float* b2L  = (const float*)d_in[8];
    const float* Wih3 = (const float*)d_in[15];
    const float* Whh3 = (const float*)d_in[16];
    const float* b3   = (const float*)d_in[17];
    const float* Wout = (const float*)d_in[18];
    const float* bout = (const float*)d_in[19];
    float* out = (float*)d_out;

    dim3 grid1(16, 4);   // N=1024 -> 16 tiles, M=256 -> 4 tiles
    dim3 grid2(8, 4);    // N=512  -> 8 tiles
    gemm1_kernel<<<grid1, 256>>>(x, W1L, b1L);
    gemm2_kernel<<<grid2, 256>>>(W2L, b2L);
    lstm_kernel<<<128, 416>>>(Wih3, Whh3, b3, Wout, bout, out);
}